// round 8
// baseline (speedup 1.0000x reference)
#include <cuda_runtime.h>
#include <cuda_fp16.h>

// RoIMaskAlign via NHWC-fp16 staging, round 8: half-width lanes for true MLP=8
// + high occupancy.
// features (B=2, C=256, H=200, W=272) fp32, rois (K, 5) fp32
// out (K, C, 14, 14) fp32
// PH=PW=14, SPATIAL_SCALE=0.25, SR=2, SPATIAL_SHIFT=0, HALF_PART=0, ROI_SCALE=1.2

#define PH 14
#define PW 14

static constexpr int   Bc = 2;
static constexpr int   Cc = 256;
static constexpr int   Hc = 200;
static constexpr int   Wc = 272;
static constexpr float SCALE     = 0.25f;
static constexpr float ROI_SCALE = 1.2f;

// NHWC fp16 scratch: (B, H, W, C) = 2*200*272*256 halves = 55.7 MB
__device__ __align__(16) __half g_nhwc[(size_t)Bc * Hc * Wc * Cc];

// ---------------------------------------------------------------------------
// Kernel 1: NCHW fp32 -> NHWC fp16 transpose (unchanged).
// ---------------------------------------------------------------------------
__global__ __launch_bounds__(256)
void transpose_kernel(const float* __restrict__ feat)
{
    __shared__ __align__(16) __half s[16][264];

    int x0 = blockIdx.x * 16;
    int y  = blockIdx.y;
    int b  = blockIdx.z;
    int tid = threadIdx.x;
    int xl = tid & 15;
    int ci = tid >> 4;

    const float* fp = feat + (((size_t)b * Cc) * Hc + y) * Wc + x0 + xl;
    #pragma unroll
    for (int k = 0; k < 16; k++) {
        int c = k * 16 + ci;
        s[xl][c] = __float2half_rn(__ldg(fp + (size_t)c * (Hc * Wc)));
    }
    __syncthreads();

    __half* op = g_nhwc + (((size_t)b * Hc + y) * Wc + x0) * Cc;
    #pragma unroll
    for (int j = 0; j < 2; j++) {
        int u = tid + j * 256;
        int x = u >> 5;
        int k = u & 31;
        *reinterpret_cast<uint4*>(op + (size_t)x * Cc + k * 8) =
            *reinterpret_cast<const uint4*>(&s[x][k * 8]);
    }
}

// Accumulate 4 fp16 channels of one tap.
__device__ __forceinline__ void acc_tap4(const uint2& v, float wt,
                                         float& a0, float& a1,
                                         float& a2, float& a3)
{
    const __half2* h = reinterpret_cast<const __half2*>(&v);
    float2 f0 = __half22float2(h[0]);
    float2 f1 = __half22float2(h[1]);
    a0 = fmaf(wt, f0.x, a0); a1 = fmaf(wt, f0.y, a1);
    a2 = fmaf(wt, f1.x, a2); a3 = fmaf(wt, f1.y, a3);
}

// ---------------------------------------------------------------------------
// Kernel 2: gather. Block = (n, ph); 28 warps (896 thr).
// warp w: pw = w>>1, channel half = w&1 (128 ch). Lane owns 4 channels
// (uint2 = 8B). 8 tap loads per sy issued back-to-back = MLP 8 at only
// 16 regs of in-flight data. Branch-free (validity folded into weights).
// ---------------------------------------------------------------------------
__global__ __launch_bounds__(896, 2)
void gather_kernel(const float* __restrict__ rois,
                   float* __restrict__ out)
{
    __shared__ __align__(16) float s[PW][264];

    int n  = blockIdx.x;
    int ph = blockIdx.y;
    int wid  = threadIdx.x >> 5;   // 0..27
    int lane = threadIdx.x & 31;
    int pw   = wid >> 1;           // 0..13
    int half = wid & 1;            // channel half

    // ---- ROI geometry (identical across the warp) ----
    const float* r = rois + n * 5;
    int   b  = (int)r[0];
    float rx1 = r[1], ry1 = r[2], rx2 = r[3], ry2 = r[4];

    float cx = (rx1 + rx2) * 0.5f;
    float cy = (ry1 + ry2) * 0.5f;
    float rw = (rx2 - rx1) * ROI_SCALE;
    float rh = (ry2 - ry1) * ROI_SCALE;
    float x1s = (cx - 0.5f * rw) * SCALE;
    float x2s = (cx + 0.5f * rw) * SCALE;
    float y1s = (cy - 0.5f * rh) * SCALE;
    float y2s = (cy + 0.5f * rh) * SCALE;

    float roi_w = fmaxf(x2s - x1s, 1.0f);
    float roi_h = fmaxf(y2s - y1s, 1.0f);
    float bin_w = roi_w * (1.0f / PW);
    float bin_h = roi_h * (1.0f / PH);

    int chan = half * 128 + lane * 4;           // first channel this lane owns
    const __half* tb = g_nhwc + chan;

    float a0 = 0.f, a1 = 0.f, a2 = 0.f, a3 = 0.f;

    // per-sample x data (shared across sy)
    int   xi0[2], xi1[2];
    float lx[2], hx[2];
    float mx[2];                 // 0.25 if x-valid else 0 (mean folded in)
    #pragma unroll
    for (int sx = 0; sx < 2; sx++) {
        float x = x1s + ((float)pw + ((float)sx + 0.5f) * 0.5f) * bin_w;
        mx[sx] = ((x > -1.0f) && (x < (float)Wc)) ? 0.25f : 0.0f;
        float xc = fminf(fmaxf(x, 0.0f), (float)(Wc - 1));
        int x0 = (int)floorf(xc);
        xi0[sx] = x0;
        xi1[sx] = min(x0 + 1, Wc - 1);
        lx[sx] = xc - (float)x0;
        hx[sx] = 1.0f - lx[sx];
    }

    #pragma unroll
    for (int sy = 0; sy < 2; sy++) {
        float y = y1s + ((float)ph + (sy ? 0.75f : 0.25f)) * bin_h;
        float vyf = ((y > -1.0f) && (y < (float)Hc)) ? 1.0f : 0.0f;
        float yc = fminf(fmaxf(y, 0.0f), (float)(Hc - 1));
        int y0 = (int)floorf(yc);
        int y1b = min(y0 + 1, Hc - 1);
        float ly = yc - (float)y0;
        float hy = 1.0f - ly;

        size_t rb0 = ((size_t)(b * Hc + y0)  * Wc) << 8;
        size_t rb1 = ((size_t)(b * Hc + y1b) * Wc) << 8;

        float m0 = vyf * mx[0];
        float m1 = vyf * mx[1];
        float wA00 = m0 * hy * hx[0], wA01 = m0 * hy * lx[0];
        float wA10 = m0 * ly * hx[0], wA11 = m0 * ly * lx[0];
        float wB00 = m1 * hy * hx[1], wB01 = m1 * hy * lx[1];
        float wB10 = m1 * ly * hx[1], wB11 = m1 * ly * lx[1];

        // 8 loads back-to-back: 8 x uint2 = 16 regs in flight (MLP = 8)
        uint2 vA00 = __ldg((const uint2*)(tb + rb0 + (((size_t)xi0[0]) << 8)));
        uint2 vA01 = __ldg((const uint2*)(tb + rb0 + (((size_t)xi1[0]) << 8)));
        uint2 vA10 = __ldg((const uint2*)(tb + rb1 + (((size_t)xi0[0]) << 8)));
        uint2 vA11 = __ldg((const uint2*)(tb + rb1 + (((size_t)xi1[0]) << 8)));
        uint2 vB00 = __ldg((const uint2*)(tb + rb0 + (((size_t)xi0[1]) << 8)));
        uint2 vB01 = __ldg((const uint2*)(tb + rb0 + (((size_t)xi1[1]) << 8)));
        uint2 vB10 = __ldg((const uint2*)(tb + rb1 + (((size_t)xi0[1]) << 8)));
        uint2 vB11 = __ldg((const uint2*)(tb + rb1 + (((size_t)xi1[1]) << 8)));

        acc_tap4(vA00, wA00, a0, a1, a2, a3);
        acc_tap4(vA01, wA01, a0, a1, a2, a3);
        acc_tap4(vA10, wA10, a0, a1, a2, a3);
        acc_tap4(vA11, wA11, a0, a1, a2, a3);
        acc_tap4(vB00, wB00, a0, a1, a2, a3);
        acc_tap4(vB01, wB01, a0, a1, a2, a3);
        acc_tap4(vB10, wB10, a0, a1, a2, a3);
        acc_tap4(vB11, wB11, a0, a1, a2, a3);
    }

    // stash as (pw, c); mean already folded
    *reinterpret_cast<float4*>(&s[pw][chan]) = make_float4(a0, a1, a2, a3);

    __syncthreads();

    // out[(n*C + c)*196 + ph*14 + pw]
    if (threadIdx.x < Cc) {
        int c = threadIdx.x;
        size_t o = ((size_t)n * Cc + c) * (PH * PW) + ph * PW;
        #pragma unroll
        for (int p = 0; p < 7; p++) {
            *reinterpret_cast<float2*>(out + o + 2 * p) =
                make_float2(s[2 * p][c], s[2 * p + 1][c]);
        }
    }
}

extern "C" void kernel_launch(void* const* d_in, const int* in_sizes, int n_in,
                              void* d_out, int out_size)
{
    const float* feat = (const float*)d_in[0];
    const float* rois = (const float*)d_in[1];
    float* out = (float*)d_out;

    int K = in_sizes[1] / 5;

    dim3 tg(Wc / 16, Hc, Bc);          // 17 x 200 x 2
    transpose_kernel<<<tg, 256>>>(feat);

    dim3 gg(K, PH);                    // K x 14
    gather_kernel<<<gg, 896>>>(rois, out);
}

// round 9
// speedup vs baseline: 1.3785x; 1.3785x over previous
#include <cuda_runtime.h>
#include <cuda_fp16.h>

// RoIMaskAlign via NHWC-fp16 staging, round 9: R5 gather core + coalesced
// output writes (block = ROI x ph-pair, smem re-staging by channel).
// features (B=2, C=256, H=200, W=272) fp32, rois (K, 5) fp32
// out (K, C, 14, 14) fp32

#define PH 14
#define PW 14

static constexpr int   Bc = 2;
static constexpr int   Cc = 256;
static constexpr int   Hc = 200;
static constexpr int   Wc = 272;
static constexpr float SCALE     = 0.25f;
static constexpr float ROI_SCALE = 1.2f;

// NHWC fp16 scratch: (B, H, W, C) = 2*200*272*256 halves = 55.7 MB
__device__ __align__(16) __half g_nhwc[(size_t)Bc * Hc * Wc * Cc];

// ---------------------------------------------------------------------------
// Kernel 1: NCHW fp32 -> NHWC fp16 transpose (unchanged; ~30us).
// ---------------------------------------------------------------------------
__global__ __launch_bounds__(256)
void transpose_kernel(const float* __restrict__ feat)
{
    __shared__ __align__(16) __half s[16][264];

    int x0 = blockIdx.x * 16;
    int y  = blockIdx.y;
    int b  = blockIdx.z;
    int tid = threadIdx.x;
    int xl = tid & 15;
    int ci = tid >> 4;

    const float* fp = feat + (((size_t)b * Cc) * Hc + y) * Wc + x0 + xl;
    #pragma unroll
    for (int k = 0; k < 16; k++) {
        int c = k * 16 + ci;
        s[xl][c] = __float2half_rn(__ldg(fp + (size_t)c * (Hc * Wc)));
    }
    __syncthreads();

    __half* op = g_nhwc + (((size_t)b * Hc + y) * Wc + x0) * Cc;
    #pragma unroll
    for (int j = 0; j < 2; j++) {
        int u = tid + j * 256;
        int x = u >> 5;
        int k = u & 31;
        *reinterpret_cast<uint4*>(op + (size_t)x * Cc + k * 8) =
            *reinterpret_cast<const uint4*>(&s[x][k * 8]);
    }
}

// ---------------------------------------------------------------------------
// Kernel 2: gather. Block = (n, php) where php = ph/2; 14 warps (448 thr).
// Warp w: ph_local = w/7, pw pair = (w%7)*2 + i. Per-warp inner loop is the
// R5 code verbatim (best measured). Results staged to smem s[c][bin] and
// written out coalesced (28 contiguous floats per channel).
// ---------------------------------------------------------------------------
static constexpr int BINS = 28;     // 2 ph x 14 pw per block
static constexpr int SSTR = 33;     // smem stride (floats) per channel

__global__ __launch_bounds__(448, 2)
void gather_kernel(const float* __restrict__ rois,
                   float* __restrict__ out)
{
    __shared__ float s[Cc * SSTR];   // 256*33*4 = 33.8 KB

    int n   = blockIdx.x;
    int php = blockIdx.y;            // 0..6
    int wid  = threadIdx.x >> 5;     // 0..13
    int lane = threadIdx.x & 31;
    int ph_l   = wid / 7;            // 0..1
    int pwpair = wid % 7;            // 0..6
    int ph  = php * 2 + ph_l;

    // ---- ROI geometry (identical across the warp) ----
    const float* r = rois + n * 5;
    int   b  = (int)r[0];
    float rx1 = r[1], ry1 = r[2], rx2 = r[3], ry2 = r[4];

    float cx = (rx1 + rx2) * 0.5f;
    float cy = (ry1 + ry2) * 0.5f;
    float rw = (rx2 - rx1) * ROI_SCALE;
    float rh = (ry2 - ry1) * ROI_SCALE;
    float x1s = (cx - 0.5f * rw) * SCALE;
    float x2s = (cx + 0.5f * rw) * SCALE;
    float y1s = (cy - 0.5f * rh) * SCALE;
    float y2s = (cy + 0.5f * rh) * SCALE;

    float roi_w = fmaxf(x2s - x1s, 1.0f);
    float roi_h = fmaxf(y2s - y1s, 1.0f);
    float bin_w = roi_w * (1.0f / PW);
    float bin_h = roi_h * (1.0f / PH);

    const __half* tb = g_nhwc;

    #pragma unroll
    for (int i = 0; i < 2; i++) {
        int pw  = pwpair * 2 + i;
        int bin = ph_l * PW + pw;

        float a0=0.f,a1=0.f,a2=0.f,a3=0.f,a4=0.f,a5=0.f,a6=0.f,a7=0.f;

        // per-sample x data (shared across sy)
        int   xi0[2], xi1[2];
        float lx[2], hx[2];
        bool  vx[2];
        #pragma unroll
        for (int sx = 0; sx < 2; sx++) {
            float x = x1s + ((float)pw + ((float)sx + 0.5f) * 0.5f) * bin_w;
            vx[sx] = (x > -1.0f) && (x < (float)Wc);
            float xc = fminf(fmaxf(x, 0.0f), (float)(Wc - 1));
            int x0 = (int)floorf(xc);
            xi0[sx] = x0;
            xi1[sx] = min(x0 + 1, Wc - 1);
            lx[sx] = xc - (float)x0;
            hx[sx] = 1.0f - lx[sx];
        }

        #define TAP(pix, wt) do {                                               \
            if ((wt) != 0.0f) {                                                 \
                uint4 v = *reinterpret_cast<const uint4*>(                      \
                    tb + (((size_t)(pix)) << 8) + lane * 8);                    \
                const __half2* hp = reinterpret_cast<const __half2*>(&v);       \
                float2 f0 = __half22float2(hp[0]);                              \
                float2 f1 = __half22float2(hp[1]);                              \
                float2 f2 = __half22float2(hp[2]);                              \
                float2 f3 = __half22float2(hp[3]);                              \
                a0 = fmaf((wt), f0.x, a0); a1 = fmaf((wt), f0.y, a1);           \
                a2 = fmaf((wt), f1.x, a2); a3 = fmaf((wt), f1.y, a3);           \
                a4 = fmaf((wt), f2.x, a4); a5 = fmaf((wt), f2.y, a5);           \
                a6 = fmaf((wt), f3.x, a6); a7 = fmaf((wt), f3.y, a7);           \
            }                                                                   \
        } while (0)

        #pragma unroll
        for (int sy = 0; sy < 2; sy++) {
            float y = y1s + ((float)ph + (sy ? 0.75f : 0.25f)) * bin_h;
            bool vy = (y > -1.0f) && (y < (float)Hc);
            float yc = fminf(fmaxf(y, 0.0f), (float)(Hc - 1));
            int y0 = (int)floorf(yc);
            int y1b = min(y0 + 1, Hc - 1);
            float ly = yc - (float)y0;
            float hy = 1.0f - ly;

            int rb0 = (b * Hc + y0)  * Wc;
            int rb1 = (b * Hc + y1b) * Wc;

            #pragma unroll
            for (int sx = 0; sx < 2; sx++) {
                float wq = (vy && vx[sx]) ? 1.0f : 0.0f;   // warp-uniform
                float w00 = wq * hy * hx[sx];
                float w01 = wq * hy * lx[sx];
                float w10 = wq * ly * hx[sx];
                float w11 = wq * ly * lx[sx];
                TAP(rb0 + xi0[sx], w00);
                TAP(rb0 + xi1[sx], w01);
                TAP(rb1 + xi0[sx], w10);
                TAP(rb1 + xi1[sx], w11);
            }
        }
        #undef TAP

        // stage as s[c][bin], mean folded here
        int c0 = lane * 8;
        s[(c0 + 0) * SSTR + bin] = a0 * 0.25f;
        s[(c0 + 1) * SSTR + bin] = a1 * 0.25f;
        s[(c0 + 2) * SSTR + bin] = a2 * 0.25f;
        s[(c0 + 3) * SSTR + bin] = a3 * 0.25f;
        s[(c0 + 4) * SSTR + bin] = a4 * 0.25f;
        s[(c0 + 5) * SSTR + bin] = a5 * 0.25f;
        s[(c0 + 6) * SSTR + bin] = a6 * 0.25f;
        s[(c0 + 7) * SSTR + bin] = a7 * 0.25f;
    }

    __syncthreads();

    // coalesced output: per channel, 28 contiguous floats
    // out[(n*Cc + c)*196 + php*28 + bin]
    for (int c = wid; c < Cc; c += 14) {
        if (lane < BINS) {
            out[((size_t)n * Cc + c) * (PH * PW) + php * BINS + lane] =
                s[c * SSTR + lane];
        }
    }
}

extern "C" void kernel_launch(void* const* d_in, const int* in_sizes, int n_in,
                              void* d_out, int out_size)
{
    const float* feat = (const float*)d_in[0];
    const float* rois = (const float*)d_in[1];
    float* out = (float*)d_out;

    int K = in_sizes[1] / 5;

    dim3 tg(Wc / 16, Hc, Bc);          // 17 x 200 x 2
    transpose_kernel<<<tg, 256>>>(feat);

    dim3 gg(K, PH / 2);                // K x 7
    gather_kernel<<<gg, 448>>>(rois, out);
}

// round 10
// speedup vs baseline: 1.4211x; 1.0309x over previous
#include <cuda_runtime.h>
#include <cuda_fp16.h>

// RoIMaskAlign via NHWC-fp16 staging, round 10: R9 + conflict-free smem
// staging (bin-major, stride 260, STS.128) + weight-folded mean.
// features (B=2, C=256, H=200, W=272) fp32, rois (K, 5) fp32
// out (K, C, 14, 14) fp32

#define PH 14
#define PW 14

static constexpr int   Bc = 2;
static constexpr int   Cc = 256;
static constexpr int   Hc = 200;
static constexpr int   Wc = 272;
static constexpr float SCALE     = 0.25f;
static constexpr float ROI_SCALE = 1.2f;

// NHWC fp16 scratch: (B, H, W, C) = 2*200*272*256 halves = 55.7 MB
__device__ __align__(16) __half g_nhwc[(size_t)Bc * Hc * Wc * Cc];

// ---------------------------------------------------------------------------
// Kernel 1: NCHW fp32 -> NHWC fp16 transpose (unchanged; near DRAM ceiling).
// ---------------------------------------------------------------------------
__global__ __launch_bounds__(256)
void transpose_kernel(const float* __restrict__ feat)
{
    __shared__ __align__(16) __half s[16][264];

    int x0 = blockIdx.x * 16;
    int y  = blockIdx.y;
    int b  = blockIdx.z;
    int tid = threadIdx.x;
    int xl = tid & 15;
    int ci = tid >> 4;

    const float* fp = feat + (((size_t)b * Cc) * Hc + y) * Wc + x0 + xl;
    #pragma unroll
    for (int k = 0; k < 16; k++) {
        int c = k * 16 + ci;
        s[xl][c] = __float2half_rn(__ldg(fp + (size_t)c * (Hc * Wc)));
    }
    __syncthreads();

    __half* op = g_nhwc + (((size_t)b * Hc + y) * Wc + x0) * Cc;
    #pragma unroll
    for (int j = 0; j < 2; j++) {
        int u = tid + j * 256;
        int x = u >> 5;
        int k = u & 31;
        *reinterpret_cast<uint4*>(op + (size_t)x * Cc + k * 8) =
            *reinterpret_cast<const uint4*>(&s[x][k * 8]);
    }
}

// ---------------------------------------------------------------------------
// Kernel 2: gather. Block = (n, php), php = ph/2; 14 warps (448 thr).
// Warp w: ph_local = w/7, handles pw = (w%7)*2 + {0,1}. Lane owns 8
// channels (uint4 taps). Staging: bin-major s[bin*260 + c], STS.128
// conflict-free; output reads column (stride 260, 4-way) + coalesced STG.
// ---------------------------------------------------------------------------
static constexpr int BINS = 28;     // 2 ph x 14 pw per block
static constexpr int SSTR = 260;    // floats per bin row (16B-aligned rows)

__global__ __launch_bounds__(448, 2)
void gather_kernel(const float* __restrict__ rois,
                   float* __restrict__ out)
{
    __shared__ __align__(16) float s[BINS * SSTR];   // 28*260*4 = 29120 B

    int n   = blockIdx.x;
    int php = blockIdx.y;            // 0..6
    int wid  = threadIdx.x >> 5;     // 0..13
    int lane = threadIdx.x & 31;
    int ph_l   = wid / 7;            // 0..1
    int pwpair = wid % 7;            // 0..6
    int ph  = php * 2 + ph_l;

    // ---- ROI geometry (identical across the warp) ----
    const float* r = rois + n * 5;
    int   b  = (int)r[0];
    float rx1 = r[1], ry1 = r[2], rx2 = r[3], ry2 = r[4];

    float cx = (rx1 + rx2) * 0.5f;
    float cy = (ry1 + ry2) * 0.5f;
    float rw = (rx2 - rx1) * ROI_SCALE;
    float rh = (ry2 - ry1) * ROI_SCALE;
    float x1s = (cx - 0.5f * rw) * SCALE;
    float x2s = (cx + 0.5f * rw) * SCALE;
    float y1s = (cy - 0.5f * rh) * SCALE;
    float y2s = (cy + 0.5f * rh) * SCALE;

    float roi_w = fmaxf(x2s - x1s, 1.0f);
    float roi_h = fmaxf(y2s - y1s, 1.0f);
    float bin_w = roi_w * (1.0f / PW);
    float bin_h = roi_h * (1.0f / PH);

    const __half* tb = g_nhwc;

    #pragma unroll
    for (int i = 0; i < 2; i++) {
        int pw  = pwpair * 2 + i;
        int bin = ph_l * PW + pw;

        float a0=0.f,a1=0.f,a2=0.f,a3=0.f,a4=0.f,a5=0.f,a6=0.f,a7=0.f;

        // per-sample x data (shared across sy)
        int   xi0[2], xi1[2];
        float lx[2], hx[2];
        bool  vx[2];
        #pragma unroll
        for (int sx = 0; sx < 2; sx++) {
            float x = x1s + ((float)pw + ((float)sx + 0.5f) * 0.5f) * bin_w;
            vx[sx] = (x > -1.0f) && (x < (float)Wc);
            float xc = fminf(fmaxf(x, 0.0f), (float)(Wc - 1));
            int x0 = (int)floorf(xc);
            xi0[sx] = x0;
            xi1[sx] = min(x0 + 1, Wc - 1);
            lx[sx] = xc - (float)x0;
            hx[sx] = 1.0f - lx[sx];
        }

        #define TAP(pix, wt) do {                                               \
            if ((wt) != 0.0f) {                                                 \
                uint4 v = *reinterpret_cast<const uint4*>(                      \
                    tb + (((size_t)(pix)) << 8) + lane * 8);                    \
                const __half2* hp = reinterpret_cast<const __half2*>(&v);       \
                float2 f0 = __half22float2(hp[0]);                              \
                float2 f1 = __half22float2(hp[1]);                              \
                float2 f2 = __half22float2(hp[2]);                              \
                float2 f3 = __half22float2(hp[3]);                              \
                a0 = fmaf((wt), f0.x, a0); a1 = fmaf((wt), f0.y, a1);           \
                a2 = fmaf((wt), f1.x, a2); a3 = fmaf((wt), f1.y, a3);           \
                a4 = fmaf((wt), f2.x, a4); a5 = fmaf((wt), f2.y, a5);           \
                a6 = fmaf((wt), f3.x, a6); a7 = fmaf((wt), f3.y, a7);           \
            }                                                                   \
        } while (0)

        #pragma unroll
        for (int sy = 0; sy < 2; sy++) {
            float y = y1s + ((float)ph + (sy ? 0.75f : 0.25f)) * bin_h;
            bool vy = (y > -1.0f) && (y < (float)Hc);
            float yc = fminf(fmaxf(y, 0.0f), (float)(Hc - 1));
            int y0 = (int)floorf(yc);
            int y1b = min(y0 + 1, Hc - 1);
            float ly = yc - (float)y0;
            float hy = 1.0f - ly;

            int rb0 = (b * Hc + y0)  * Wc;
            int rb1 = (b * Hc + y1b) * Wc;

            #pragma unroll
            for (int sx = 0; sx < 2; sx++) {
                float wq = (vy && vx[sx]) ? 0.25f : 0.0f;  // validity + mean
                float w00 = wq * hy * hx[sx];
                float w01 = wq * hy * lx[sx];
                float w10 = wq * ly * hx[sx];
                float w11 = wq * ly * lx[sx];
                TAP(rb0 + xi0[sx], w00);
                TAP(rb0 + xi1[sx], w01);
                TAP(rb1 + xi0[sx], w10);
                TAP(rb1 + xi1[sx], w11);
            }
        }
        #undef TAP

        // stage bin-major: two aligned STS.128, conflict-free
        float* dst = s + bin * SSTR + lane * 8;
        *reinterpret_cast<float4*>(dst)     = make_float4(a0, a1, a2, a3);
        *reinterpret_cast<float4*>(dst + 4) = make_float4(a4, a5, a6, a7);
    }

    __syncthreads();

    // coalesced output: per channel, 28 contiguous floats
    // out[(n*Cc + c)*196 + php*28 + bin], bin = lane
    for (int c = wid; c < Cc; c += 14) {
        if (lane < BINS) {
            out[((size_t)n * Cc + c) * (PH * PW) + php * BINS + lane] =
                s[lane * SSTR + c];
        }
    }
}

extern "C" void kernel_launch(void* const* d_in, const int* in_sizes, int n_in,
                              void* d_out, int out_size)
{
    const float* feat = (const float*)d_in[0];
    const float* rois = (const float*)d_in[1];
    float* out = (float*)d_out;

    int K = in_sizes[1] / 5;

    dim3 tg(Wc / 16, Hc, Bc);          // 17 x 200 x 2
    transpose_kernel<<<tg, 256>>>(feat);

    dim3 gg(K, PH / 2);                // K x 7
    gather_kernel<<<gg, 448>>>(rois, out);
}